// round 9
// baseline (speedup 1.0000x reference)
#include <cuda_runtime.h>
#include <cuda_bf16.h>
#include <math.h>

// ---------------------------------------------------------------------------
// FAM: out[b,o,h,w] = bias[o] + sum_{kk,c} w[o,c,kk] * bilin(u[b,c], p+kk+off)
// Restructured: V_kk = W_kk @ U  (dense GEMM), then bilinear-gather V.
// B=8, C=128, H=W=64, k=3 (K=9). All fp32.
// ---------------------------------------------------------------------------

#define Bsz 8
#define Cch 128
#define Hh 64
#define Ww 64
#define HW 4096
#define KK 9
#define OCH 18   // offset channels = 2*KK

// Scratch (static device arrays: allocation APIs are forbidden)
__device__ float g_off[(size_t)Bsz * OCH * HW];            // [b][18][h][w]
__device__ float g_wT [(size_t)KK * Cch * Cch];            // [kk][c][o]
__device__ float g_v  [(size_t)Bsz * KK * HW * Cch];       // [b][kk][p][o]  channel-last

// ---------------------------------------------------------------------------
// Kernel 0: weight transpose  weight[o][c][ky][kx] -> wT[kk][c][o]
// ---------------------------------------------------------------------------
__global__ void wt_kernel(const float* __restrict__ w) {
    int idx = blockIdx.x * 256 + threadIdx.x;
    if (idx >= KK * Cch * Cch) return;
    int kk = idx / (Cch * Cch);
    int r  = idx % (Cch * Cch);
    int c  = r >> 7;
    int o  = r & 127;
    g_wT[idx] = w[((o << 7) + c) * 9 + kk];
}

// ---------------------------------------------------------------------------
// Kernel 1: offset conv (3x3, pad 1): concat(x,u)[256ch] -> g_off[18ch]
// Block: 256 thr = 16x16 pixel tile, one per pixel, 18 accumulators.
// Channel chunks of 16 staged in smem; weight rows vectorized (float4 LDS).
// ---------------------------------------------------------------------------
__global__ __launch_bounds__(256) void offset_conv_kernel(
    const float* __restrict__ x, const float* __restrict__ u,
    const float* __restrict__ ow, const float* __restrict__ ob)
{
    __shared__ float s_in[16][18][18];   // 16ch x 18x18 halo tile
    __shared__ float s_w [16][9][20];    // [ci][kj][oc] (oc padded to 20)

    int b  = blockIdx.z;
    int h0 = blockIdx.y * 16, w0 = blockIdx.x * 16;
    int tid = threadIdx.x;
    int ty = tid >> 4, tx = tid & 15;

    float acc[18];
    #pragma unroll
    for (int oc = 0; oc < 18; ++oc) acc[oc] = ob[oc];

    for (int chunk = 0; chunk < 16; ++chunk) {
        const float* src = (chunk < 8) ? x : u;
        int cbase = (chunk & 7) * 16;
        // input halo tile
        for (int idx = tid; idx < 16 * 324; idx += 256) {
            int ci = idx / 324, r = idx % 324;
            int yy = r / 18, xx = r % 18;
            int gy = h0 - 1 + yy, gx = w0 - 1 + xx;
            float v = 0.f;
            if ((unsigned)gy < 64u && (unsigned)gx < 64u)
                v = src[(((size_t)b * Cch + cbase + ci) << 12) + (gy << 6) + gx];
            s_in[ci][yy][xx] = v;
        }
        // weights: ow[oc][ic][ky][kx], ic global channel
        int icg0 = (chunk < 8) ? cbase : (128 + cbase);
        for (int idx = tid; idx < 16 * 162; idx += 256) {
            int ci = idx / 162, r = idx % 162;
            int kj = r / 18, oc = r % 18;
            s_w[ci][kj][oc] = ow[(oc * 256 + icg0 + ci) * 9 + kj];
        }
        __syncthreads();

        #pragma unroll 1
        for (int ci = 0; ci < 16; ++ci) {
            float in9[9];
            #pragma unroll
            for (int kj = 0; kj < 9; ++kj)
                in9[kj] = s_in[ci][ty + kj / 3][tx + kj % 3];
            #pragma unroll
            for (int kj = 0; kj < 9; ++kj) {
                const float4* wr = (const float4*)&s_w[ci][kj][0];
                float4 w0v = wr[0], w1v = wr[1], w2v = wr[2], w3v = wr[3];
                float w16 = s_w[ci][kj][16], w17 = s_w[ci][kj][17];
                float iv = in9[kj];
                acc[0]  += iv * w0v.x; acc[1]  += iv * w0v.y;
                acc[2]  += iv * w0v.z; acc[3]  += iv * w0v.w;
                acc[4]  += iv * w1v.x; acc[5]  += iv * w1v.y;
                acc[6]  += iv * w1v.z; acc[7]  += iv * w1v.w;
                acc[8]  += iv * w2v.x; acc[9]  += iv * w2v.y;
                acc[10] += iv * w2v.z; acc[11] += iv * w2v.w;
                acc[12] += iv * w3v.x; acc[13] += iv * w3v.y;
                acc[14] += iv * w3v.z; acc[15] += iv * w3v.w;
                acc[16] += iv * w16;   acc[17] += iv * w17;
            }
        }
        __syncthreads();
    }

    int h = h0 + ty, w = w0 + tx;
    float* dst = g_off + (size_t)b * OCH * HW + (h << 6) + w;
    #pragma unroll
    for (int oc = 0; oc < 18; ++oc)
        dst[(size_t)oc * HW] = acc[oc];
}

// ---------------------------------------------------------------------------
// Kernel 2: V_kk[p][o] = sum_c wT[kk][c][o] * u[b][c][p]
// Block: 256 thr computes [128 o x 64 px] tile for all 9 kk (U tile reused).
// 8x4 register tile per thread. smem transpose -> coalesced channel-last store.
// Dynamic smem: Us 32KB + Ws 64KB = 96KB.
// ---------------------------------------------------------------------------
__global__ __launch_bounds__(256) void gemm_kernel(const float* __restrict__ u)
{
    extern __shared__ float smem[];
    float* Us = smem;          // [128c][64px]
    float* Ws = smem + 8192;   // [128c][128o], reused as Ct[64px][128o]

    int b  = blockIdx.y;
    int p0 = blockIdx.x * 64;
    int tid = threadIdx.x;
    int i = tid >> 4;          // o-group (8 rows)
    int j = tid & 15;          // px-group (4 cols)

    // load U tile (coalesced, float4)
    const float4* u4 = (const float4*)(u + (size_t)b * Cch * HW + p0);
    for (int idx = tid; idx < 2048; idx += 256) {
        int c = idx >> 4, q = idx & 15;
        ((float4*)Us)[c * 16 + q] = u4[c * 1024 + q];
    }
    __syncthreads();

    for (int kk = 0; kk < KK; ++kk) {
        const float4* wsrc = (const float4*)(g_wT + (size_t)kk * Cch * Cch);
        for (int idx = tid; idx < 4096; idx += 256)
            ((float4*)Ws)[idx] = wsrc[idx];
        __syncthreads();

        float acc[8][4];
        #pragma unroll
        for (int r = 0; r < 8; ++r)
            #pragma unroll
            for (int q = 0; q < 4; ++q) acc[r][q] = 0.f;

        #pragma unroll 2
        for (int c = 0; c < 128; ++c) {
            float4 uu = *(const float4*)&Us[c * 64 + j * 4];
            float4 wA = *(const float4*)&Ws[c * 128 + i * 8];
            float4 wB = *(const float4*)&Ws[c * 128 + i * 8 + 4];
            float uv[4] = {uu.x, uu.y, uu.z, uu.w};
            float wv[8] = {wA.x, wA.y, wA.z, wA.w, wB.x, wB.y, wB.z, wB.w};
            #pragma unroll
            for (int r = 0; r < 8; ++r)
                #pragma unroll
                for (int q = 0; q < 4; ++q)
                    acc[r][q] += wv[r] * uv[q];
        }
        __syncthreads();   // everyone done reading Ws

        // transpose: Ct[px][o]
        #pragma unroll
        for (int r = 0; r < 8; ++r)
            #pragma unroll
            for (int q = 0; q < 4; ++q)
                Ws[(j * 4 + q) * 128 + i * 8 + r] = acc[r][q];
        __syncthreads();

        // coalesced store: one 512B row (128 o) per px
        float* vout = g_v + ((size_t)(b * KK + kk) * HW + p0) * Cch;
        int warp = tid >> 5, lane = tid & 31;
        #pragma unroll
        for (int r8 = 0; r8 < 8; ++r8) {
            int row = warp * 8 + r8;
            float4 val = ((const float4*)Ws)[row * 32 + lane];
            ((float4*)(vout + (size_t)row * 128))[lane] = val;
        }
        __syncthreads();
    }
}

// ---------------------------------------------------------------------------
// Kernel 3: gather + combine.
// Block: (h row, b), 128 thr (o = tid), loop 64 px.
// out[b,o,h,w] = bias[o] + sum_kk sum_corners cw * v[b,kk,corner,o]
// smem transpose for coalesced NCHW writes.
// ---------------------------------------------------------------------------
__global__ __launch_bounds__(128) void gather_kernel(
    const float* __restrict__ bias, float* __restrict__ out)
{
    int h = blockIdx.x, b = blockIdx.y;
    int tid = threadIdx.x;
    __shared__ float sm[64][129];

    float bv = bias[tid];
    const float* offb = g_off + (size_t)b * OCH * HW + (h << 6);
    const float* vbb  = g_v + (size_t)b * KK * HW * Cch + tid;

    for (int w = 0; w < 64; ++w) {
        float a0 = bv, a1 = 0.f, a2 = 0.f, a3 = 0.f;
        #pragma unroll
        for (int kk = 0; kk < 9; ++kk) {
            float dy = offb[(size_t)(2 * kk) * HW + w];
            float dx = offb[(size_t)(2 * kk + 1) * HW + w];
            float spy = (float)(h - 1 + kk / 3) + dy;
            float spx = (float)(w - 1 + kk % 3) + dx;
            float y0f = floorf(spy), x0f = floorf(spx);
            int y0 = (int)y0f, x0 = (int)x0f;
            float wy1 = spy - y0f, wx1 = spx - x0f;
            float wy0 = 1.f - wy1, wx0 = 1.f - wx1;

            bool vy0 = (y0 >= 0) && (y0 < 64);
            bool vy1 = (y0 + 1 >= 0) && (y0 + 1 < 64);
            bool vx0 = (x0 >= 0) && (x0 < 64);
            bool vx1 = (x0 + 1 >= 0) && (x0 + 1 < 64);
            int y0c = min(max(y0, 0), 63),     y1c = min(max(y0 + 1, 0), 63);
            int x0c = min(max(x0, 0), 63),     x1c = min(max(x0 + 1, 0), 63);

            const float* vb = vbb + (size_t)kk * HW * Cch;
            if (vy0 && vx0) a0 += (wy0 * wx0) * vb[(size_t)((y0c << 6) + x0c) * 128];
            if (vy0 && vx1) a1 += (wy0 * wx1) * vb[(size_t)((y0c << 6) + x1c) * 128];
            if (vy1 && vx0) a2 += (wy1 * wx0) * vb[(size_t)((y1c << 6) + x0c) * 128];
            if (vy1 && vx1) a3 += (wy1 * wx1) * vb[(size_t)((y1c << 6) + x1c) * 128];
        }
        sm[w][tid] = (a0 + a1) + (a2 + a3);
    }
    __syncthreads();

    // coalesced write-out: out[b][o][h][0..63]
    #pragma unroll 4
    for (int ob = 0; ob < 128; ob += 2) {
        int o  = ob + (tid >> 6);
        int ww = tid & 63;
        out[(((size_t)(b * 128 + o) << 6) + h) * 64 + ww] = sm[ww][o];
    }
}

// ---------------------------------------------------------------------------
extern "C" void kernel_launch(void* const* d_in, const int* in_sizes, int n_in,
                              void* d_out, int out_size)
{
    const float* x      = (const float*)d_in[0];
    const float* u      = (const float*)d_in[1];
    const float* weight = (const float*)d_in[2];
    const float* bias   = (const float*)d_in[3];
    const float* ow     = (const float*)d_in[4];
    const float* ob     = (const float*)d_in[5];
    float* out = (float*)d_out;

    cudaFuncSetAttribute(gemm_kernel,
        cudaFuncAttributeMaxDynamicSharedMemorySize, 98304);

    wt_kernel<<<(KK * Cch * Cch + 255) / 256, 256>>>(weight);
    offset_conv_kernel<<<dim3(4, 4, Bsz), 256>>>(x, u, ow, ob);
    gemm_kernel<<<dim3(HW / 64, Bsz), 256, 98304>>>(u);
    gather_kernel<<<dim3(Hh, Bsz), 128>>>(bias, out);
}

// round 10
// speedup vs baseline: 1.0022x; 1.0022x over previous
#include <cuda_runtime.h>
#include <cuda_bf16.h>
#include <math.h>

// ---------------------------------------------------------------------------
// FAM: out[b,o,h,w] = bias[o] + sum_{kk,c} w[o,c,kk] * bilin(u[b,c], p+kk+off)
// Restructured: V_kk = W_kk @ U  (dense GEMM), then bilinear-gather V.
// B=8, C=128, H=W=64, k=3 (K=9). All fp32.
// ---------------------------------------------------------------------------

#define Bsz 8
#define Cch 128
#define Hh 64
#define Ww 64
#define HW 4096
#define KK 9
#define OCH 18   // offset channels = 2*KK

// Scratch (static device arrays: allocation APIs are forbidden)
__device__ float g_off[(size_t)Bsz * OCH * HW];            // [b][18][h][w]
__device__ float g_wT [(size_t)KK * Cch * Cch];            // [kk][c][o]
__device__ float g_v  [(size_t)Bsz * KK * HW * Cch];       // [b][kk][p][o]  channel-last

// ---------------------------------------------------------------------------
// Kernel 0: weight transpose  weight[o][c][ky][kx] -> wT[kk][c][o]
// ---------------------------------------------------------------------------
__global__ void wt_kernel(const float* __restrict__ w) {
    int idx = blockIdx.x * 256 + threadIdx.x;
    if (idx >= KK * Cch * Cch) return;
    int kk = idx / (Cch * Cch);
    int r  = idx % (Cch * Cch);
    int c  = r >> 7;
    int o  = r & 127;
    g_wT[idx] = w[((o << 7) + c) * 9 + kk];
}

// ---------------------------------------------------------------------------
// Kernel 1: offset conv (3x3, pad 1): concat(x,u)[256ch] -> g_off[18ch]
// Block: 256 thr = 16x16 pixel tile, one per pixel, 18 accumulators.
// Channel chunks of 16 staged in smem; weight rows vectorized (float4 LDS).
// ---------------------------------------------------------------------------
__global__ __launch_bounds__(256) void offset_conv_kernel(
    const float* __restrict__ x, const float* __restrict__ u,
    const float* __restrict__ ow, const float* __restrict__ ob)
{
    __shared__ float s_in[16][18][18];   // 16ch x 18x18 halo tile
    __shared__ float s_w [16][9][20];    // [ci][kj][oc] (oc padded to 20)

    int b  = blockIdx.z;
    int h0 = blockIdx.y * 16, w0 = blockIdx.x * 16;
    int tid = threadIdx.x;
    int ty = tid >> 4, tx = tid & 15;

    float acc[18];
    #pragma unroll
    for (int oc = 0; oc < 18; ++oc) acc[oc] = ob[oc];

    for (int chunk = 0; chunk < 16; ++chunk) {
        const float* src = (chunk < 8) ? x : u;
        int cbase = (chunk & 7) * 16;
        // input halo tile
        for (int idx = tid; idx < 16 * 324; idx += 256) {
            int ci = idx / 324, r = idx % 324;
            int yy = r / 18, xx = r % 18;
            int gy = h0 - 1 + yy, gx = w0 - 1 + xx;
            float v = 0.f;
            if ((unsigned)gy < 64u && (unsigned)gx < 64u)
                v = src[(((size_t)b * Cch + cbase + ci) << 12) + (gy << 6) + gx];
            s_in[ci][yy][xx] = v;
        }
        // weights: ow[oc][ic][ky][kx], ic global channel
        int icg0 = (chunk < 8) ? cbase : (128 + cbase);
        for (int idx = tid; idx < 16 * 162; idx += 256) {
            int ci = idx / 162, r = idx % 162;
            int kj = r / 18, oc = r % 18;
            s_w[ci][kj][oc] = ow[(oc * 256 + icg0 + ci) * 9 + kj];
        }
        __syncthreads();

        #pragma unroll 1
        for (int ci = 0; ci < 16; ++ci) {
            float in9[9];
            #pragma unroll
            for (int kj = 0; kj < 9; ++kj)
                in9[kj] = s_in[ci][ty + kj / 3][tx + kj % 3];
            #pragma unroll
            for (int kj = 0; kj < 9; ++kj) {
                const float4* wr = (const float4*)&s_w[ci][kj][0];
                float4 w0v = wr[0], w1v = wr[1], w2v = wr[2], w3v = wr[3];
                float w16 = s_w[ci][kj][16], w17 = s_w[ci][kj][17];
                float iv = in9[kj];
                acc[0]  += iv * w0v.x; acc[1]  += iv * w0v.y;
                acc[2]  += iv * w0v.z; acc[3]  += iv * w0v.w;
                acc[4]  += iv * w1v.x; acc[5]  += iv * w1v.y;
                acc[6]  += iv * w1v.z; acc[7]  += iv * w1v.w;
                acc[8]  += iv * w2v.x; acc[9]  += iv * w2v.y;
                acc[10] += iv * w2v.z; acc[11] += iv * w2v.w;
                acc[12] += iv * w3v.x; acc[13] += iv * w3v.y;
                acc[14] += iv * w3v.z; acc[15] += iv * w3v.w;
                acc[16] += iv * w16;   acc[17] += iv * w17;
            }
        }
        __syncthreads();
    }

    int h = h0 + ty, w = w0 + tx;
    float* dst = g_off + (size_t)b * OCH * HW + (h << 6) + w;
    #pragma unroll
    for (int oc = 0; oc < 18; ++oc)
        dst[(size_t)oc * HW] = acc[oc];
}

// ---------------------------------------------------------------------------
// Kernel 2: V_kk[p][o] = sum_c wT[kk][c][o] * u[b][c][p]
// Block: 256 thr computes [128 o x 64 px] tile for all 9 kk (U tile reused).
// 8x4 register tile per thread. smem transpose -> coalesced channel-last store.
// Dynamic smem: Us 32KB + Ws 64KB = 96KB.
// ---------------------------------------------------------------------------
__global__ __launch_bounds__(256) void gemm_kernel(const float* __restrict__ u)
{
    extern __shared__ float smem[];
    float* Us = smem;          // [128c][64px]
    float* Ws = smem + 8192;   // [128c][128o], reused as Ct[64px][128o]

    int b  = blockIdx.y;
    int p0 = blockIdx.x * 64;
    int tid = threadIdx.x;
    int i = tid >> 4;          // o-group (8 rows)
    int j = tid & 15;          // px-group (4 cols)

    // load U tile (coalesced, float4)
    const float4* u4 = (const float4*)(u + (size_t)b * Cch * HW + p0);
    for (int idx = tid; idx < 2048; idx += 256) {
        int c = idx >> 4, q = idx & 15;
        ((float4*)Us)[c * 16 + q] = u4[c * 1024 + q];
    }
    __syncthreads();

    for (int kk = 0; kk < KK; ++kk) {
        const float4* wsrc = (const float4*)(g_wT + (size_t)kk * Cch * Cch);
        for (int idx = tid; idx < 4096; idx += 256)
            ((float4*)Ws)[idx] = wsrc[idx];
        __syncthreads();

        float acc[8][4];
        #pragma unroll
        for (int r = 0; r < 8; ++r)
            #pragma unroll
            for (int q = 0; q < 4; ++q) acc[r][q] = 0.f;

        #pragma unroll 2
        for (int c = 0; c < 128; ++c) {
            float4 uu = *(const float4*)&Us[c * 64 + j * 4];
            float4 wA = *(const float4*)&Ws[c * 128 + i * 8];
            float4 wB = *(const float4*)&Ws[c * 128 + i * 8 + 4];
            float uv[4] = {uu.x, uu.y, uu.z, uu.w};
            float wv[8] = {wA.x, wA.y, wA.z, wA.w, wB.x, wB.y, wB.z, wB.w};
            #pragma unroll
            for (int r = 0; r < 8; ++r)
                #pragma unroll
                for (int q = 0; q < 4; ++q)
                    acc[r][q] += wv[r] * uv[q];
        }
        __syncthreads();   // everyone done reading Ws

        // transpose: Ct[px][o]
        #pragma unroll
        for (int r = 0; r < 8; ++r)
            #pragma unroll
            for (int q = 0; q < 4; ++q)
                Ws[(j * 4 + q) * 128 + i * 8 + r] = acc[r][q];
        __syncthreads();

        // coalesced store: one 512B row (128 o) per px
        float* vout = g_v + ((size_t)(b * KK + kk) * HW + p0) * Cch;
        int warp = tid >> 5, lane = tid & 31;
        #pragma unroll
        for (int r8 = 0; r8 < 8; ++r8) {
            int row = warp * 8 + r8;
            float4 val = ((const float4*)Ws)[row * 32 + lane];
            ((float4*)(vout + (size_t)row * 128))[lane] = val;
        }
        __syncthreads();
    }
}

// ---------------------------------------------------------------------------
// Kernel 3: gather + combine.
// Block: (h row, b), 128 thr (o = tid), loop 64 px.
// out[b,o,h,w] = bias[o] + sum_kk sum_corners cw * v[b,kk,corner,o]
// smem transpose for coalesced NCHW writes.
// ---------------------------------------------------------------------------
__global__ __launch_bounds__(128) void gather_kernel(
    const float* __restrict__ bias, float* __restrict__ out)
{
    int h = blockIdx.x, b = blockIdx.y;
    int tid = threadIdx.x;
    __shared__ float sm[64][129];

    float bv = bias[tid];
    const float* offb = g_off + (size_t)b * OCH * HW + (h << 6);
    const float* vbb  = g_v + (size_t)b * KK * HW * Cch + tid;

    for (int w = 0; w < 64; ++w) {
        float a0 = bv, a1 = 0.f, a2 = 0.f, a3 = 0.f;
        #pragma unroll
        for (int kk = 0; kk < 9; ++kk) {
            float dy = offb[(size_t)(2 * kk) * HW + w];
            float dx = offb[(size_t)(2 * kk + 1) * HW + w];
            float spy = (float)(h - 1 + kk / 3) + dy;
            float spx = (float)(w - 1 + kk % 3) + dx;
            float y0f = floorf(spy), x0f = floorf(spx);
            int y0 = (int)y0f, x0 = (int)x0f;
            float wy1 = spy - y0f, wx1 = spx - x0f;
            float wy0 = 1.f - wy1, wx0 = 1.f - wx1;

            bool vy0 = (y0 >= 0) && (y0 < 64);
            bool vy1 = (y0 + 1 >= 0) && (y0 + 1 < 64);
            bool vx0 = (x0 >= 0) && (x0 < 64);
            bool vx1 = (x0 + 1 >= 0) && (x0 + 1 < 64);
            int y0c = min(max(y0, 0), 63),     y1c = min(max(y0 + 1, 0), 63);
            int x0c = min(max(x0, 0), 63),     x1c = min(max(x0 + 1, 0), 63);

            const float* vb = vbb + (size_t)kk * HW * Cch;
            if (vy0 && vx0) a0 += (wy0 * wx0) * vb[(size_t)((y0c << 6) + x0c) * 128];
            if (vy0 && vx1) a1 += (wy0 * wx1) * vb[(size_t)((y0c << 6) + x1c) * 128];
            if (vy1 && vx0) a2 += (wy1 * wx0) * vb[(size_t)((y1c << 6) + x0c) * 128];
            if (vy1 && vx1) a3 += (wy1 * wx1) * vb[(size_t)((y1c << 6) + x1c) * 128];
        }
        sm[w][tid] = (a0 + a1) + (a2 + a3);
    }
    __syncthreads();

    // coalesced write-out: out[b][o][h][0..63]
    #pragma unroll 4
    for (int ob = 0; ob < 128; ob += 2) {
        int o  = ob + (tid >> 6);
        int ww = tid & 63;
        out[(((size_t)(b * 128 + o) << 6) + h) * 64 + ww] = sm[ww][o];
    }
}

// ---------------------------------------------------------------------------
extern "C" void kernel_launch(void* const* d_in, const int* in_sizes, int n_in,
                              void* d_out, int out_size)
{
    const float* x      = (const float*)d_in[0];
    const float* u      = (const float*)d_in[1];
    const float* weight = (const float*)d_in[2];
    const float* bias   = (const float*)d_in[3];
    const float* ow     = (const float*)d_in[4];
    const float* ob     = (const float*)d_in[5];
    float* out = (float*)d_out;

    cudaFuncSetAttribute(gemm_kernel,
        cudaFuncAttributeMaxDynamicSharedMemorySize, 98304);

    wt_kernel<<<(KK * Cch * Cch + 255) / 256, 256>>>(weight);
    offset_conv_kernel<<<dim3(4, 4, Bsz), 256>>>(x, u, ow, ob);
    gemm_kernel<<<dim3(HW / 64, Bsz), 256, 98304>>>(u);
    gather_kernel<<<dim3(Hh, Bsz), 128>>>(bias, out);
}